// round 12
// baseline (speedup 1.0000x reference)
#include <cuda_runtime.h>

// Two Euler steps of a Gaussian-RBF point flow — single persistent kernel.
// R12 change vs R10 (passing, 26.6us): MUFU (ex2.approx.f32, measured ~rt16
// on sm_100a => ~21us chip floor for 50.3M exps) is the binding pipe. Half
// the exponentials now bypass MUFU entirely via an FFMA/ALU bit-trick exp2
// (magic-number round, deg-4 poly on [-0.5,0.5], integer exponent splice),
// alternating per j-step. Balances MUFU vs FMA pipes at ~2x MUFU headroom.
//   Phase A: dp1 PARTIALS for all 16384 land rows. 512 CTAs x 256 thr.
//   Grid barrier (monotonic counter; 512 CTAs resident at 4 CTAs/SM).
//   Phase B: dp2; staging rebuilds shape1 tables; 4-way parity combine.
// Inner exponent: safe combined form arg = u*x + v*y + a + cri <= 0.

#define NSRC  2048
#define NTGT  2048
#define NLAND 4096
#define NB    4
#define NCTA  512
#define TAUF  0.5f
#define LOG2E 1.4426950408889634f

typedef unsigned long long ull;

// Cross-phase scratch (device globals; no allocation).
__device__ float2 g_p1[2][NB * NLAND];   // dp1 partials per j-half
__device__ float2 g_p2[4][NB * NTGT];    // dp2 partials per j-quarter
__device__ ull      g_ctr;               // grid barrier, monotonic across calls
__device__ unsigned g_flag[128];         // per-group arrival count, monotonic

__device__ __forceinline__ float ex2f(float x) {
    float y;
    asm("ex2.approx.ftz.f32 %0, %1;" : "=f"(y) : "f"(x));
    return y;
}
__device__ __forceinline__ ull fma2(ull a, ull b, ull c) {
    ull d;
    asm("fma.rn.f32x2 %0, %1, %2, %3;" : "=l"(d) : "l"(a), "l"(b), "l"(c));
    return d;
}
__device__ __forceinline__ ull add2(ull a, ull b) {
    ull d;
    asm("add.rn.f32x2 %0, %1, %2;" : "=l"(d) : "l"(a), "l"(b));
    return d;
}
__device__ __forceinline__ ull pack2(float lo, float hi) {
    ull d;
    asm("mov.b64 %0, {%1, %2};" : "=l"(d) : "f"(lo), "f"(hi));
    return d;
}
__device__ __forceinline__ void unpack2(ull v, float& lo, float& hi) {
    asm("mov.b64 {%0, %1}, %2;" : "=f"(lo), "=f"(hi) : "l"(v));
}

// FFMA/ALU-pipe exp2 (no MUFU). Valid for arg <= 0 (clamped at -120).
// k = RN(arg) via magic add (0x4B400000 low-9 bits are 0 -> t_bits<<23 == k<<23
// exactly); f = arg-k in [-0.5,0.5]; deg-4 Taylor (max rel err ~6e-5);
// exponent spliced with an integer add. Clamp keeps the result normal.
__device__ __forceinline__ float fast_ex2(float a) {
    a = fmaxf(a, -120.0f);
    float t = a + 12582912.0f;            // RN -> integer k encoded in mantissa
    float r = t - 12582912.0f;            // == (float)k exactly
    float f = a - r;                      // exact, in [-0.5, 0.5]
    float p = fmaf(0.0096181291f, f, 0.0555041087f);
    p = fmaf(p, f, 0.2402265070f);
    p = fmaf(p, f, 0.6931471806f);
    p = fmaf(p, f, 1.0f);                 // 2^f, rel err <= ~6e-5
    int k23 = __float_as_int(t) << 23;    // k << 23 (exact, incl. negative k)
    return __int_as_float(__float_as_int(p) + k23);
}

// One row's packed update for a loaded j-pair. MUFU=true uses SFU ex2;
// MUFU=false uses the FFMA/ALU path (pipe balancing).
template <bool MUFU>
__device__ __forceinline__ void rbf_row(
    ull UVx, ull UVy, ull APa, ull APp, ull PY,
    ull xp, ull yp, ull crip, ull& ax, ull& ay)
{
    ull arg = add2(fma2(UVy, yp, fma2(UVx, xp, APa)), crip);
    float a0, a1;
    unpack2(arg, a0, a1);
    ull wp;
    if (MUFU) wp = pack2(ex2f(a0), ex2f(a1));
    else      wp = pack2(fast_ex2(a0), fast_ex2(a1));
    ax = fma2(wp, APp, ax);
    ay = fma2(wp, PY, ay);
}

// ---------------------------------------------------------------------------
__global__ __launch_bounds__(256, 4) void fused_kernel(
    const float2* __restrict__ mom,
    const float2* __restrict__ src,
    const float2* __restrict__ tgt,
    const float*  __restrict__ sig,
    float2*       __restrict__ out)
{
    // Layout: sUV [0,8K) | sAP [8K,16K) | sPY [16K,20K).
    // Reduction buffer (8KB) aliases sUV after a syncthreads.
    __shared__ __align__(16) char SM[20480];
    float4* sUV = (float4*)(SM);
    float4* sAP = (float4*)(SM + 8192);
    float2* sPY = (float2*)(SM + 16384);
    typedef ull RedRow[256];                 // [warp*32+lane]
    RedRow* red = (RedRow*)(SM);             // red[4][256] = 8KB, aliases sUV

    const int tid  = threadIdx.x;
    const int w    = tid >> 5;
    const int lane = tid & 31;
    const int g    = blockIdx.x;

    const float c2 = -LOG2E / sig[0];
    const float m2 = -2.0f * c2;

    // ======================= Phase A: dp1 partials =======================
    {
        const int grp = g >> 1;              // 0..255: 64-row land group
        const int sj  = g & 1;               // j-half
        const int i0  = grp * 64;            // global land row base
        const int b   = i0 >> 12;
        const int li  = i0 & (NLAND - 1);

        const float2* __restrict__ srcb = src + b * NSRC;
        const float2* __restrict__ momb = mom + b * NSRC;

        const int pbase = sj * 512;          // pair range [pbase, pbase+512)
        for (int q = tid; q < 512; q += 256) {
            const int p = pbase + q;
            float2 s0 = srcb[2 * p], s1 = srcb[2 * p + 1];
            float2 q0 = momb[2 * p], q1 = momb[2 * p + 1];
            sUV[q] = make_float4(m2 * s0.x, m2 * s1.x, m2 * s0.y, m2 * s1.y);
            sAP[q] = make_float4(c2 * (s0.x * s0.x + s0.y * s0.y),
                                 c2 * (s1.x * s1.x + s1.y * s1.y), q0.x, q1.x);
            sPY[q] = make_float2(q0.y, q1.y);
        }
        __syncthreads();

        const int r0 = li + lane, r1 = r0 + 32;     // same side of 2048
        float2 X0 = (li < NSRC) ? srcb[r0] : tgt[b * NTGT + r0 - NSRC];
        float2 X1 = (li < NSRC) ? srcb[r1] : tgt[b * NTGT + r1 - NSRC];
        const ull xp0 = pack2(X0.x, X0.x), yp0 = pack2(X0.y, X0.y);
        const ull xp1 = pack2(X1.x, X1.x), yp1 = pack2(X1.y, X1.y);
        float c0 = c2 * (X0.x * X0.x + X0.y * X0.y);
        float c1 = c2 * (X1.x * X1.x + X1.y * X1.y);
        const ull cr0 = pack2(c0, c0), cr1 = pack2(c1, c1);

        ull ax0 = 0ull, ay0 = 0ull, ax1 = 0ull, ay1 = 0ull;
        const int qb = w * 64;
        #pragma unroll 4
        for (int t = 0; t < 64; t += 2) {
            {   // even step: MUFU path
                ulonglong2 UV = *(const ulonglong2*)&sUV[qb + t];
                ulonglong2 AP = *(const ulonglong2*)&sAP[qb + t];
                ull PY = *(const ull*)&sPY[qb + t];
                rbf_row<true >(UV.x, UV.y, AP.x, AP.y, PY, xp0, yp0, cr0, ax0, ay0);
                rbf_row<true >(UV.x, UV.y, AP.x, AP.y, PY, xp1, yp1, cr1, ax1, ay1);
            }
            {   // odd step: FFMA/ALU path
                ulonglong2 UV = *(const ulonglong2*)&sUV[qb + t + 1];
                ulonglong2 AP = *(const ulonglong2*)&sAP[qb + t + 1];
                ull PY = *(const ull*)&sPY[qb + t + 1];
                rbf_row<false>(UV.x, UV.y, AP.x, AP.y, PY, xp0, yp0, cr0, ax0, ay0);
                rbf_row<false>(UV.x, UV.y, AP.x, AP.y, PY, xp1, yp1, cr1, ax1, ay1);
            }
        }
        __syncthreads();                      // table reads done; red aliases sUV
        red[0][w * 32 + lane] = ax0;
        red[1][w * 32 + lane] = ay0;
        red[2][w * 32 + lane] = ax1;
        red[3][w * 32 + lane] = ay1;
        __syncthreads();

        if (w == 0) {
            ull s0 = red[0][lane], s1 = red[1][lane];
            ull s2 = red[2][lane], s3 = red[3][lane];
            #pragma unroll
            for (int ww = 1; ww < 8; ww++) {
                s0 = add2(s0, red[0][ww * 32 + lane]);
                s1 = add2(s1, red[1][ww * 32 + lane]);
                s2 = add2(s2, red[2][ww * 32 + lane]);
                s3 = add2(s3, red[3][ww * 32 + lane]);
            }
            float e0, e1, f0, f1;
            unpack2(s0, e0, e1); unpack2(s1, f0, f1);
            g_p1[sj][i0 + lane] = make_float2(e0 + e1, f0 + f1);
            unpack2(s2, e0, e1); unpack2(s3, f0, f1);
            g_p1[sj][i0 + 32 + lane] = make_float2(e0 + e1, f0 + f1);
        }
    }

    // ======================= Grid barrier =======================
    __threadfence();
    __syncthreads();
    if (tid == 0) {
        ull old = atomicAdd(&g_ctr, 1ull);
        ull target = (old & ~(ull)(NCTA - 1)) + (ull)NCTA;
        while (*(volatile ull*)&g_ctr < target) __nanosleep(64);
        __threadfence();
    }
    __syncthreads();

    // ======================= Phase B: dp2 + output =======================
    {
        const int grp = g >> 2;              // 0..127: 64-row target group
        const int sj  = g & 3;               // j-quarter
        const int t0  = grp * 64;            // global target row base
        const int b   = t0 >> 11;

        // Stage 256 pairs, rebuilding shape1 pack from dp1 partials.
        {
            const int q = tid;               // 256 threads, 256 entries
            const int p = sj * 256 + q;      // pair within batch
            const int j0 = 2 * p, j1 = 2 * p + 1;
            const int l0 = b * NLAND + j0, l1 = b * NLAND + j1;
            float2 pa0 = g_p1[0][l0], pb0 = g_p1[1][l0];
            float2 pa1 = g_p1[0][l1], pb1 = g_p1[1][l1];
            float2 s0 = src[b * NSRC + j0], s1 = src[b * NSRC + j1];
            float2 q0 = mom[b * NSRC + j0], q1 = mom[b * NSRC + j1];
            float s0x = fmaf(TAUF, pa0.x + pb0.x, s0.x);
            float s0y = fmaf(TAUF, pa0.y + pb0.y, s0.y);
            float s1x = fmaf(TAUF, pa1.x + pb1.x, s1.x);
            float s1y = fmaf(TAUF, pa1.y + pb1.y, s1.y);
            sUV[q] = make_float4(m2 * s0x, m2 * s1x, m2 * s0y, m2 * s1y);
            sAP[q] = make_float4(c2 * (s0x * s0x + s0y * s0y),
                                 c2 * (s1x * s1x + s1y * s1y), q0.x, q1.x);
            sPY[q] = make_float2(q0.y, q1.y);
        }
        __syncthreads();

        // This lane's two target rows, advected to shape1.
        const int ta = t0 + lane, tb2 = ta + 32;
        const int rta = ta & (NTGT - 1), rtb = tb2 & (NTGT - 1);
        const int la = b * NLAND + NSRC + rta, lb = b * NLAND + NSRC + rtb;
        float2 Ta = tgt[ta], Tb = tgt[tb2];
        float2 da0 = g_p1[0][la], da1 = g_p1[1][la];
        float2 db0 = g_p1[0][lb], db1 = g_p1[1][lb];
        float2 X0 = make_float2(fmaf(TAUF, da0.x + da1.x, Ta.x),
                                fmaf(TAUF, da0.y + da1.y, Ta.y));
        float2 X1 = make_float2(fmaf(TAUF, db0.x + db1.x, Tb.x),
                                fmaf(TAUF, db0.y + db1.y, Tb.y));
        const ull xp0 = pack2(X0.x, X0.x), yp0 = pack2(X0.y, X0.y);
        const ull xp1 = pack2(X1.x, X1.x), yp1 = pack2(X1.y, X1.y);
        float c0 = c2 * (X0.x * X0.x + X0.y * X0.y);
        float c1 = c2 * (X1.x * X1.x + X1.y * X1.y);
        const ull cr0 = pack2(c0, c0), cr1 = pack2(c1, c1);

        ull ax0 = 0ull, ay0 = 0ull, ax1 = 0ull, ay1 = 0ull;
        const int qb = w * 32;
        #pragma unroll 4
        for (int t = 0; t < 32; t += 2) {
            {   // even step: MUFU path
                ulonglong2 UV = *(const ulonglong2*)&sUV[qb + t];
                ulonglong2 AP = *(const ulonglong2*)&sAP[qb + t];
                ull PY = *(const ull*)&sPY[qb + t];
                rbf_row<true >(UV.x, UV.y, AP.x, AP.y, PY, xp0, yp0, cr0, ax0, ay0);
                rbf_row<true >(UV.x, UV.y, AP.x, AP.y, PY, xp1, yp1, cr1, ax1, ay1);
            }
            {   // odd step: FFMA/ALU path
                ulonglong2 UV = *(const ulonglong2*)&sUV[qb + t + 1];
                ulonglong2 AP = *(const ulonglong2*)&sAP[qb + t + 1];
                ull PY = *(const ull*)&sPY[qb + t + 1];
                rbf_row<false>(UV.x, UV.y, AP.x, AP.y, PY, xp0, yp0, cr0, ax0, ay0);
                rbf_row<false>(UV.x, UV.y, AP.x, AP.y, PY, xp1, yp1, cr1, ax1, ay1);
            }
        }
        __syncthreads();                      // table reads done; red aliases sUV
        red[0][w * 32 + lane] = ax0;
        red[1][w * 32 + lane] = ay0;
        red[2][w * 32 + lane] = ax1;
        red[3][w * 32 + lane] = ay1;
        __syncthreads();

        if (w == 0) {
            ull s0 = red[0][lane], s1 = red[1][lane];
            ull s2 = red[2][lane], s3 = red[3][lane];
            #pragma unroll
            for (int ww = 1; ww < 8; ww++) {
                s0 = add2(s0, red[0][ww * 32 + lane]);
                s1 = add2(s1, red[1][ww * 32 + lane]);
                s2 = add2(s2, red[2][ww * 32 + lane]);
                s3 = add2(s3, red[3][ww * 32 + lane]);
            }
            float e0, e1, f0, f1;
            unpack2(s0, e0, e1); unpack2(s1, f0, f1);
            g_p2[sj][ta] = make_float2(e0 + e1, f0 + f1);
            unpack2(s2, e0, e1); unpack2(s3, f0, f1);
            g_p2[sj][tb2] = make_float2(e0 + e1, f0 + f1);

            __threadfence();                  // release partials
            __syncwarp();
            unsigned old = 0;
            if (lane == 0) old = atomicAdd(&g_flag[grp], 1u);
            old = __shfl_sync(0xffffffffu, old, 0);
            if ((old & 3u) == 3u) {           // 4th arrival: combine + writeout
                __threadfence();              // acquire peer partials
                float2 p0 = __ldcg(&g_p2[0][ta]);
                float2 p1 = __ldcg(&g_p2[1][ta]);
                float2 p2 = __ldcg(&g_p2[2][ta]);
                float2 p3 = __ldcg(&g_p2[3][ta]);
                out[ta] = make_float2(
                    fmaf(TAUF, (p0.x + p1.x) + (p2.x + p3.x), X0.x),
                    fmaf(TAUF, (p0.y + p1.y) + (p2.y + p3.y), X0.y));
                p0 = __ldcg(&g_p2[0][tb2]);
                p1 = __ldcg(&g_p2[1][tb2]);
                p2 = __ldcg(&g_p2[2][tb2]);
                p3 = __ldcg(&g_p2[3][tb2]);
                out[tb2] = make_float2(
                    fmaf(TAUF, (p0.x + p1.x) + (p2.x + p3.x), X1.x),
                    fmaf(TAUF, (p0.y + p1.y) + (p2.y + p3.y), X1.y));
            }
        }
    }
}

// ---------------------------------------------------------------------------
extern "C" void kernel_launch(void* const* d_in, const int* in_sizes, int n_in,
                              void* d_out, int out_size)
{
    const float2* mom = (const float2*)d_in[0];
    const float2* src = (const float2*)d_in[1];
    const float2* tgt = (const float2*)d_in[2];
    const float*  sig = (const float*)d_in[3];
    float2* out = (float2*)d_out;

    fused_kernel<<<NCTA, 256>>>(mom, src, tgt, sig, out);
}

// round 13
// speedup vs baseline: 1.0471x; 1.0471x over previous
#include <cuda_runtime.h>

// Two Euler steps of a Gaussian-RBF point flow — single persistent kernel.
// R13: MUFU (ex2.approx.f32, effective rt~16/SMSP on sm_100a => ~25us floor
// for 50.3M exps, exactly matching R10) is balanced against the FMA pipe by
// evaluating HALF the exponentials with a PACKED f32x2 bit-trick exp2
// (magic-number round, deg-4 poly, integer exponent splice), alternating per
// j-step. All constants are hoisted into registers (Blackwell has no free
// cbank operands; R12's scalar version paid per-use const traffic).
//   Phase A: dp1 PARTIALS for all 16384 land rows. 512 CTAs x 256 thr.
//   Grid barrier (monotonic counter; 512 CTAs resident at 4 CTAs/SM).
//   Phase B: dp2; staging rebuilds shape1 tables; 4-way parity combine.
// Inner exponent: safe combined form arg = u*x + v*y + a + cri <= 0.

#define NSRC  2048
#define NTGT  2048
#define NLAND 4096
#define NB    4
#define NCTA  512
#define TAUF  0.5f
#define LOG2E 1.4426950408889634f

typedef unsigned long long ull;

// Cross-phase scratch (device globals; no allocation).
__device__ float2 g_p1[2][NB * NLAND];   // dp1 partials per j-half
__device__ float2 g_p2[4][NB * NTGT];    // dp2 partials per j-quarter
__device__ ull      g_ctr;               // grid barrier, monotonic across calls
__device__ unsigned g_flag[128];         // per-group arrival count, monotonic

__device__ __forceinline__ float ex2f(float x) {
    float y;
    asm("ex2.approx.ftz.f32 %0, %1;" : "=f"(y) : "f"(x));
    return y;
}
__device__ __forceinline__ ull fma2(ull a, ull b, ull c) {
    ull d;
    asm("fma.rn.f32x2 %0, %1, %2, %3;" : "=l"(d) : "l"(a), "l"(b), "l"(c));
    return d;
}
__device__ __forceinline__ ull add2(ull a, ull b) {
    ull d;
    asm("add.rn.f32x2 %0, %1, %2;" : "=l"(d) : "l"(a), "l"(b));
    return d;
}
__device__ __forceinline__ ull pack2(float lo, float hi) {
    ull d;
    asm("mov.b64 %0, {%1, %2};" : "=l"(d) : "f"(lo), "f"(hi));
    return d;
}
__device__ __forceinline__ void unpack2(ull v, float& lo, float& hi) {
    asm("mov.b64 {%0, %1}, %2;" : "=f"(lo), "=f"(hi) : "l"(v));
}

// Hoisted packed constants for the FFMA-pipe exp2 (kept in registers).
struct ExC {
    ull magic, nmagic, c4, c3, c2, c1, one;
};
__device__ __forceinline__ ExC make_exc() {
    ExC C;
    C.magic  = pack2(12582912.0f, 12582912.0f);    // 1.5 * 2^23
    C.nmagic = pack2(-12582912.0f, -12582912.0f);
    C.c4 = pack2(0.0096181291f, 0.0096181291f);
    C.c3 = pack2(0.0555041087f, 0.0555041087f);
    C.c2 = pack2(0.2402265070f, 0.2402265070f);
    C.c1 = pack2(0.6931471806f, 0.6931471806f);
    C.one = pack2(1.0f, 1.0f);
    return C;
}

// Packed FFMA/ALU-pipe exp2 for BOTH halves of a2 (args <= 0, clamped -120).
// k = RN(a) via magic add; f = a - k in [-0.5,0.5]; deg-4 poly (rel ~6e-5);
// exponent spliced by integer add of (t_bits << 23) per half (magic's low 9
// bits are zero, so the shift yields exactly k<<23).
__device__ __forceinline__ ull fast_ex2_pair(ull a2, const ExC& C) {
    float a0, a1;
    unpack2(a2, a0, a1);
    a0 = fmaxf(a0, -120.0f);
    a1 = fmaxf(a1, -120.0f);
    ull ap = pack2(a0, a1);
    ull t = add2(ap, C.magic);           // RN(a) encoded in mantissa
    ull r = add2(t, C.nmagic);           // (float)k, exact
    float r0, r1;
    unpack2(r, r0, r1);
    ull fp = pack2(a0 - r0, a1 - r1);    // exact, in [-0.5, 0.5]
    ull p = fma2(C.c4, fp, C.c3);
    p = fma2(p, fp, C.c2);
    p = fma2(p, fp, C.c1);
    p = fma2(p, fp, C.one);              // 2^f
    unsigned tlo, thi, plo, phi;
    asm("mov.b64 {%0,%1}, %2;" : "=r"(tlo), "=r"(thi) : "l"(t));
    asm("mov.b64 {%0,%1}, %2;" : "=r"(plo), "=r"(phi) : "l"(p));
    unsigned wlo = plo + (tlo << 23);
    unsigned whi = phi + (thi << 23);
    ull w;
    asm("mov.b64 %0, {%1,%2};" : "=l"(w) : "r"(wlo), "r"(whi));
    return w;
}

// One row's packed update for a loaded j-pair. MUFU=true uses SFU ex2;
// MUFU=false uses the packed FFMA/ALU path (pipe balancing).
template <bool MUFU>
__device__ __forceinline__ void rbf_row(
    ull UVx, ull UVy, ull APa, ull APp, ull PY,
    ull xp, ull yp, ull crip, const ExC& C, ull& ax, ull& ay)
{
    ull arg = add2(fma2(UVy, yp, fma2(UVx, xp, APa)), crip);
    ull wp;
    if (MUFU) {
        float a0, a1;
        unpack2(arg, a0, a1);
        wp = pack2(ex2f(a0), ex2f(a1));
    } else {
        wp = fast_ex2_pair(arg, C);
    }
    ax = fma2(wp, APp, ax);
    ay = fma2(wp, PY, ay);
}

// ---------------------------------------------------------------------------
__global__ __launch_bounds__(256, 4) void fused_kernel(
    const float2* __restrict__ mom,
    const float2* __restrict__ src,
    const float2* __restrict__ tgt,
    const float*  __restrict__ sig,
    float2*       __restrict__ out)
{
    // Layout: sUV [0,8K) | sAP [8K,16K) | sPY [16K,20K).
    // Reduction buffer (8KB) aliases sUV after a syncthreads.
    __shared__ __align__(16) char SM[20480];
    float4* sUV = (float4*)(SM);
    float4* sAP = (float4*)(SM + 8192);
    float2* sPY = (float2*)(SM + 16384);
    typedef ull RedRow[256];                 // [warp*32+lane]
    RedRow* red = (RedRow*)(SM);             // red[4][256] = 8KB, aliases sUV

    const int tid  = threadIdx.x;
    const int w    = tid >> 5;
    const int lane = tid & 31;
    const int g    = blockIdx.x;

    const float c2 = -LOG2E / sig[0];
    const float m2 = -2.0f * c2;
    const ExC C = make_exc();                // packed consts live in registers

    // ======================= Phase A: dp1 partials =======================
    {
        const int grp = g >> 1;              // 0..255: 64-row land group
        const int sj  = g & 1;               // j-half
        const int i0  = grp * 64;            // global land row base
        const int b   = i0 >> 12;
        const int li  = i0 & (NLAND - 1);

        const float2* __restrict__ srcb = src + b * NSRC;
        const float2* __restrict__ momb = mom + b * NSRC;

        const int pbase = sj * 512;          // pair range [pbase, pbase+512)
        for (int q = tid; q < 512; q += 256) {
            const int p = pbase + q;
            float2 s0 = srcb[2 * p], s1 = srcb[2 * p + 1];
            float2 q0 = momb[2 * p], q1 = momb[2 * p + 1];
            sUV[q] = make_float4(m2 * s0.x, m2 * s1.x, m2 * s0.y, m2 * s1.y);
            sAP[q] = make_float4(c2 * (s0.x * s0.x + s0.y * s0.y),
                                 c2 * (s1.x * s1.x + s1.y * s1.y), q0.x, q1.x);
            sPY[q] = make_float2(q0.y, q1.y);
        }
        __syncthreads();

        const int r0 = li + lane, r1 = r0 + 32;     // same side of 2048
        float2 X0 = (li < NSRC) ? srcb[r0] : tgt[b * NTGT + r0 - NSRC];
        float2 X1 = (li < NSRC) ? srcb[r1] : tgt[b * NTGT + r1 - NSRC];
        const ull xp0 = pack2(X0.x, X0.x), yp0 = pack2(X0.y, X0.y);
        const ull xp1 = pack2(X1.x, X1.x), yp1 = pack2(X1.y, X1.y);
        float c0 = c2 * (X0.x * X0.x + X0.y * X0.y);
        float c1 = c2 * (X1.x * X1.x + X1.y * X1.y);
        const ull cr0 = pack2(c0, c0), cr1 = pack2(c1, c1);

        ull ax0 = 0ull, ay0 = 0ull, ax1 = 0ull, ay1 = 0ull;
        const int qb = w * 64;
        #pragma unroll 4
        for (int t = 0; t < 64; t += 2) {
            {   // even step: MUFU path
                ulonglong2 UV = *(const ulonglong2*)&sUV[qb + t];
                ulonglong2 AP = *(const ulonglong2*)&sAP[qb + t];
                ull PY = *(const ull*)&sPY[qb + t];
                rbf_row<true >(UV.x, UV.y, AP.x, AP.y, PY, xp0, yp0, cr0, C, ax0, ay0);
                rbf_row<true >(UV.x, UV.y, AP.x, AP.y, PY, xp1, yp1, cr1, C, ax1, ay1);
            }
            {   // odd step: packed FFMA/ALU path
                ulonglong2 UV = *(const ulonglong2*)&sUV[qb + t + 1];
                ulonglong2 AP = *(const ulonglong2*)&sAP[qb + t + 1];
                ull PY = *(const ull*)&sPY[qb + t + 1];
                rbf_row<false>(UV.x, UV.y, AP.x, AP.y, PY, xp0, yp0, cr0, C, ax0, ay0);
                rbf_row<false>(UV.x, UV.y, AP.x, AP.y, PY, xp1, yp1, cr1, C, ax1, ay1);
            }
        }
        __syncthreads();                      // table reads done; red aliases sUV
        red[0][w * 32 + lane] = ax0;
        red[1][w * 32 + lane] = ay0;
        red[2][w * 32 + lane] = ax1;
        red[3][w * 32 + lane] = ay1;
        __syncthreads();

        if (w == 0) {
            ull s0 = red[0][lane], s1 = red[1][lane];
            ull s2 = red[2][lane], s3 = red[3][lane];
            #pragma unroll
            for (int ww = 1; ww < 8; ww++) {
                s0 = add2(s0, red[0][ww * 32 + lane]);
                s1 = add2(s1, red[1][ww * 32 + lane]);
                s2 = add2(s2, red[2][ww * 32 + lane]);
                s3 = add2(s3, red[3][ww * 32 + lane]);
            }
            float e0, e1, f0, f1;
            unpack2(s0, e0, e1); unpack2(s1, f0, f1);
            g_p1[sj][i0 + lane] = make_float2(e0 + e1, f0 + f1);
            unpack2(s2, e0, e1); unpack2(s3, f0, f1);
            g_p1[sj][i0 + 32 + lane] = make_float2(e0 + e1, f0 + f1);
        }
    }

    // ======================= Grid barrier =======================
    __threadfence();
    __syncthreads();
    if (tid == 0) {
        ull old = atomicAdd(&g_ctr, 1ull);
        ull target = (old & ~(ull)(NCTA - 1)) + (ull)NCTA;
        while (*(volatile ull*)&g_ctr < target) __nanosleep(64);
        __threadfence();
    }
    __syncthreads();

    // ======================= Phase B: dp2 + output =======================
    {
        const int grp = g >> 2;              // 0..127: 64-row target group
        const int sj  = g & 3;               // j-quarter
        const int t0  = grp * 64;            // global target row base
        const int b   = t0 >> 11;

        // Stage 256 pairs, rebuilding shape1 pack from dp1 partials.
        {
            const int q = tid;               // 256 threads, 256 entries
            const int p = sj * 256 + q;      // pair within batch
            const int j0 = 2 * p, j1 = 2 * p + 1;
            const int l0 = b * NLAND + j0, l1 = b * NLAND + j1;
            float2 pa0 = g_p1[0][l0], pb0 = g_p1[1][l0];
            float2 pa1 = g_p1[0][l1], pb1 = g_p1[1][l1];
            float2 s0 = src[b * NSRC + j0], s1 = src[b * NSRC + j1];
            float2 q0 = mom[b * NSRC + j0], q1 = mom[b * NSRC + j1];
            float s0x = fmaf(TAUF, pa0.x + pb0.x, s0.x);
            float s0y = fmaf(TAUF, pa0.y + pb0.y, s0.y);
            float s1x = fmaf(TAUF, pa1.x + pb1.x, s1.x);
            float s1y = fmaf(TAUF, pa1.y + pb1.y, s1.y);
            sUV[q] = make_float4(m2 * s0x, m2 * s1x, m2 * s0y, m2 * s1y);
            sAP[q] = make_float4(c2 * (s0x * s0x + s0y * s0y),
                                 c2 * (s1x * s1x + s1y * s1y), q0.x, q1.x);
            sPY[q] = make_float2(q0.y, q1.y);
        }
        __syncthreads();

        // This lane's two target rows, advected to shape1.
        const int ta = t0 + lane, tb2 = ta + 32;
        const int rta = ta & (NTGT - 1), rtb = tb2 & (NTGT - 1);
        const int la = b * NLAND + NSRC + rta, lb = b * NLAND + NSRC + rtb;
        float2 Ta = tgt[ta], Tb = tgt[tb2];
        float2 da0 = g_p1[0][la], da1 = g_p1[1][la];
        float2 db0 = g_p1[0][lb], db1 = g_p1[1][lb];
        float2 X0 = make_float2(fmaf(TAUF, da0.x + da1.x, Ta.x),
                                fmaf(TAUF, da0.y + da1.y, Ta.y));
        float2 X1 = make_float2(fmaf(TAUF, db0.x + db1.x, Tb.x),
                                fmaf(TAUF, db0.y + db1.y, Tb.y));
        const ull xp0 = pack2(X0.x, X0.x), yp0 = pack2(X0.y, X0.y);
        const ull xp1 = pack2(X1.x, X1.x), yp1 = pack2(X1.y, X1.y);
        float c0 = c2 * (X0.x * X0.x + X0.y * X0.y);
        float c1 = c2 * (X1.x * X1.x + X1.y * X1.y);
        const ull cr0 = pack2(c0, c0), cr1 = pack2(c1, c1);

        ull ax0 = 0ull, ay0 = 0ull, ax1 = 0ull, ay1 = 0ull;
        const int qb = w * 32;
        #pragma unroll 4
        for (int t = 0; t < 32; t += 2) {
            {   // even step: MUFU path
                ulonglong2 UV = *(const ulonglong2*)&sUV[qb + t];
                ulonglong2 AP = *(const ulonglong2*)&sAP[qb + t];
                ull PY = *(const ull*)&sPY[qb + t];
                rbf_row<true >(UV.x, UV.y, AP.x, AP.y, PY, xp0, yp0, cr0, C, ax0, ay0);
                rbf_row<true >(UV.x, UV.y, AP.x, AP.y, PY, xp1, yp1, cr1, C, ax1, ay1);
            }
            {   // odd step: packed FFMA/ALU path
                ulonglong2 UV = *(const ulonglong2*)&sUV[qb + t + 1];
                ulonglong2 AP = *(const ulonglong2*)&sAP[qb + t + 1];
                ull PY = *(const ull*)&sPY[qb + t + 1];
                rbf_row<false>(UV.x, UV.y, AP.x, AP.y, PY, xp0, yp0, cr0, C, ax0, ay0);
                rbf_row<false>(UV.x, UV.y, AP.x, AP.y, PY, xp1, yp1, cr1, C, ax1, ay1);
            }
        }
        __syncthreads();                      // table reads done; red aliases sUV
        red[0][w * 32 + lane] = ax0;
        red[1][w * 32 + lane] = ay0;
        red[2][w * 32 + lane] = ax1;
        red[3][w * 32 + lane] = ay1;
        __syncthreads();

        if (w == 0) {
            ull s0 = red[0][lane], s1 = red[1][lane];
            ull s2 = red[2][lane], s3 = red[3][lane];
            #pragma unroll
            for (int ww = 1; ww < 8; ww++) {
                s0 = add2(s0, red[0][ww * 32 + lane]);
                s1 = add2(s1, red[1][ww * 32 + lane]);
                s2 = add2(s2, red[2][ww * 32 + lane]);
                s3 = add2(s3, red[3][ww * 32 + lane]);
            }
            float e0, e1, f0, f1;
            unpack2(s0, e0, e1); unpack2(s1, f0, f1);
            g_p2[sj][ta] = make_float2(e0 + e1, f0 + f1);
            unpack2(s2, e0, e1); unpack2(s3, f0, f1);
            g_p2[sj][tb2] = make_float2(e0 + e1, f0 + f1);

            __threadfence();                  // release partials
            __syncwarp();
            unsigned old = 0;
            if (lane == 0) old = atomicAdd(&g_flag[grp], 1u);
            old = __shfl_sync(0xffffffffu, old, 0);
            if ((old & 3u) == 3u) {           // 4th arrival: combine + writeout
                __threadfence();              // acquire peer partials
                float2 p0 = __ldcg(&g_p2[0][ta]);
                float2 p1 = __ldcg(&g_p2[1][ta]);
                float2 p2 = __ldcg(&g_p2[2][ta]);
                float2 p3 = __ldcg(&g_p2[3][ta]);
                out[ta] = make_float2(
                    fmaf(TAUF, (p0.x + p1.x) + (p2.x + p3.x), X0.x),
                    fmaf(TAUF, (p0.y + p1.y) + (p2.y + p3.y), X0.y));
                p0 = __ldcg(&g_p2[0][tb2]);
                p1 = __ldcg(&g_p2[1][tb2]);
                p2 = __ldcg(&g_p2[2][tb2]);
                p3 = __ldcg(&g_p2[3][tb2]);
                out[tb2] = make_float2(
                    fmaf(TAUF, (p0.x + p1.x) + (p2.x + p3.x), X1.x),
                    fmaf(TAUF, (p0.y + p1.y) + (p2.y + p3.y), X1.y));
            }
        }
    }
}

// ---------------------------------------------------------------------------
extern "C" void kernel_launch(void* const* d_in, const int* in_sizes, int n_in,
                              void* d_out, int out_size)
{
    const float2* mom = (const float2*)d_in[0];
    const float2* src = (const float2*)d_in[1];
    const float2* tgt = (const float2*)d_in[2];
    const float*  sig = (const float*)d_in[3];
    float2* out = (float2*)d_out;

    fused_kernel<<<NCTA, 256>>>(mom, src, tgt, sig, out);
}

// round 14
// speedup vs baseline: 1.1394x; 1.0881x over previous
#include <cuda_runtime.h>

// Two Euler steps of a Gaussian-RBF point flow — single persistent kernel.
// R14: calibrated pipe-balance. Measured machine model (13 rounds of data):
//   ex2.approx.f32 rt=16/SMSP (R10's 25.4us == that floor exactly);
//   packed f32x2 math cracks into 2 fma-pipe uops (R13's 1:1 offload went
//   fma-bound at 31us, matching the crack model).
// Optimal offload fraction x* = balance of MUFU(42.4K·(1-x)) vs
// FMA(26.5K + 42.4K·x) cyc/SMSP => x ~= 0.22. Implemented as every 4th
// j-step using the packed FFMA/ALU exp2 (deg-4 poly + exponent splice),
// the rest on MUFU. Everything else identical to R13 (passed, 2.4e-5).
//   Phase A: dp1 PARTIALS for all 16384 land rows. 512 CTAs x 256 thr.
//   Grid barrier (monotonic counter; 512 CTAs resident at 4 CTAs/SM).
//   Phase B: dp2; staging rebuilds shape1 tables; 4-way parity combine.
// Inner exponent: safe combined form arg = u*x + v*y + a + cri <= 0.

#define NSRC  2048
#define NTGT  2048
#define NLAND 4096
#define NB    4
#define NCTA  512
#define TAUF  0.5f
#define LOG2E 1.4426950408889634f

typedef unsigned long long ull;

// Cross-phase scratch (device globals; no allocation).
__device__ float2 g_p1[2][NB * NLAND];   // dp1 partials per j-half
__device__ float2 g_p2[4][NB * NTGT];    // dp2 partials per j-quarter
__device__ ull      g_ctr;               // grid barrier, monotonic across calls
__device__ unsigned g_flag[128];         // per-group arrival count, monotonic

__device__ __forceinline__ float ex2f(float x) {
    float y;
    asm("ex2.approx.ftz.f32 %0, %1;" : "=f"(y) : "f"(x));
    return y;
}
__device__ __forceinline__ ull fma2(ull a, ull b, ull c) {
    ull d;
    asm("fma.rn.f32x2 %0, %1, %2, %3;" : "=l"(d) : "l"(a), "l"(b), "l"(c));
    return d;
}
__device__ __forceinline__ ull add2(ull a, ull b) {
    ull d;
    asm("add.rn.f32x2 %0, %1, %2;" : "=l"(d) : "l"(a), "l"(b));
    return d;
}
__device__ __forceinline__ ull pack2(float lo, float hi) {
    ull d;
    asm("mov.b64 %0, {%1, %2};" : "=l"(d) : "f"(lo), "f"(hi));
    return d;
}
__device__ __forceinline__ void unpack2(ull v, float& lo, float& hi) {
    asm("mov.b64 {%0, %1}, %2;" : "=f"(lo), "=f"(hi) : "l"(v));
}

// Hoisted packed constants for the FFMA-pipe exp2 (kept in registers).
struct ExC {
    ull magic, nmagic, c4, c3, c2, c1, one;
};
__device__ __forceinline__ ExC make_exc() {
    ExC C;
    C.magic  = pack2(12582912.0f, 12582912.0f);    // 1.5 * 2^23
    C.nmagic = pack2(-12582912.0f, -12582912.0f);
    C.c4 = pack2(0.0096181291f, 0.0096181291f);
    C.c3 = pack2(0.0555041087f, 0.0555041087f);
    C.c2 = pack2(0.2402265070f, 0.2402265070f);
    C.c1 = pack2(0.6931471806f, 0.6931471806f);
    C.one = pack2(1.0f, 1.0f);
    return C;
}

// Packed FFMA/ALU-pipe exp2 for BOTH halves of a2 (args <= 0, clamped -120).
// k = RN(a) via magic add; f = a - k in [-0.5,0.5]; deg-4 poly (rel ~6e-5);
// exponent spliced by integer add of (t_bits << 23) per half.
__device__ __forceinline__ ull fast_ex2_pair(ull a2, const ExC& C) {
    float a0, a1;
    unpack2(a2, a0, a1);
    a0 = fmaxf(a0, -120.0f);
    a1 = fmaxf(a1, -120.0f);
    ull ap = pack2(a0, a1);
    ull t = add2(ap, C.magic);           // RN(a) encoded in mantissa
    ull r = add2(t, C.nmagic);           // (float)k, exact
    float r0, r1;
    unpack2(r, r0, r1);
    ull fp = pack2(a0 - r0, a1 - r1);    // exact, in [-0.5, 0.5]
    ull p = fma2(C.c4, fp, C.c3);
    p = fma2(p, fp, C.c2);
    p = fma2(p, fp, C.c1);
    p = fma2(p, fp, C.one);              // 2^f
    unsigned tlo, thi, plo, phi;
    asm("mov.b64 {%0,%1}, %2;" : "=r"(tlo), "=r"(thi) : "l"(t));
    asm("mov.b64 {%0,%1}, %2;" : "=r"(plo), "=r"(phi) : "l"(p));
    unsigned wlo = plo + (tlo << 23);
    unsigned whi = phi + (thi << 23);
    ull w;
    asm("mov.b64 %0, {%1,%2};" : "=l"(w) : "r"(wlo), "r"(whi));
    return w;
}

// One row's packed update for a loaded j-pair. MUFU=true uses SFU ex2;
// MUFU=false uses the packed FFMA/ALU path (pipe balancing).
template <bool MUFU>
__device__ __forceinline__ void rbf_row(
    ull UVx, ull UVy, ull APa, ull APp, ull PY,
    ull xp, ull yp, ull crip, const ExC& C, ull& ax, ull& ay)
{
    ull arg = add2(fma2(UVy, yp, fma2(UVx, xp, APa)), crip);
    ull wp;
    if (MUFU) {
        float a0, a1;
        unpack2(arg, a0, a1);
        wp = pack2(ex2f(a0), ex2f(a1));
    } else {
        wp = fast_ex2_pair(arg, C);
    }
    ax = fma2(wp, APp, ax);
    ay = fma2(wp, PY, ay);
}

// One j-step (both rows) with selectable exp path.
template <bool MUFU>
__device__ __forceinline__ void rbf_step(
    const float4* __restrict__ sUV, const float4* __restrict__ sAP,
    const float2* __restrict__ sPY, int q,
    ull xp0, ull yp0, ull cr0, ull xp1, ull yp1, ull cr1,
    const ExC& C, ull& ax0, ull& ay0, ull& ax1, ull& ay1)
{
    ulonglong2 UV = *(const ulonglong2*)&sUV[q];
    ulonglong2 AP = *(const ulonglong2*)&sAP[q];
    ull PY = *(const ull*)&sPY[q];
    rbf_row<MUFU>(UV.x, UV.y, AP.x, AP.y, PY, xp0, yp0, cr0, C, ax0, ay0);
    rbf_row<MUFU>(UV.x, UV.y, AP.x, AP.y, PY, xp1, yp1, cr1, C, ax1, ay1);
}

// ---------------------------------------------------------------------------
__global__ __launch_bounds__(256, 4) void fused_kernel(
    const float2* __restrict__ mom,
    const float2* __restrict__ src,
    const float2* __restrict__ tgt,
    const float*  __restrict__ sig,
    float2*       __restrict__ out)
{
    // Layout: sUV [0,8K) | sAP [8K,16K) | sPY [16K,20K).
    // Reduction buffer (8KB) aliases sUV after a syncthreads.
    __shared__ __align__(16) char SM[20480];
    float4* sUV = (float4*)(SM);
    float4* sAP = (float4*)(SM + 8192);
    float2* sPY = (float2*)(SM + 16384);
    typedef ull RedRow[256];                 // [warp*32+lane]
    RedRow* red = (RedRow*)(SM);             // red[4][256] = 8KB, aliases sUV

    const int tid  = threadIdx.x;
    const int w    = tid >> 5;
    const int lane = tid & 31;
    const int g    = blockIdx.x;

    const float c2 = -LOG2E / sig[0];
    const float m2 = -2.0f * c2;
    const ExC C = make_exc();                // packed consts live in registers

    // ======================= Phase A: dp1 partials =======================
    {
        const int grp = g >> 1;              // 0..255: 64-row land group
        const int sj  = g & 1;               // j-half
        const int i0  = grp * 64;            // global land row base
        const int b   = i0 >> 12;
        const int li  = i0 & (NLAND - 1);

        const float2* __restrict__ srcb = src + b * NSRC;
        const float2* __restrict__ momb = mom + b * NSRC;

        const int pbase = sj * 512;          // pair range [pbase, pbase+512)
        for (int q = tid; q < 512; q += 256) {
            const int p = pbase + q;
            float2 s0 = srcb[2 * p], s1 = srcb[2 * p + 1];
            float2 q0 = momb[2 * p], q1 = momb[2 * p + 1];
            sUV[q] = make_float4(m2 * s0.x, m2 * s1.x, m2 * s0.y, m2 * s1.y);
            sAP[q] = make_float4(c2 * (s0.x * s0.x + s0.y * s0.y),
                                 c2 * (s1.x * s1.x + s1.y * s1.y), q0.x, q1.x);
            sPY[q] = make_float2(q0.y, q1.y);
        }
        __syncthreads();

        const int r0 = li + lane, r1 = r0 + 32;     // same side of 2048
        float2 X0 = (li < NSRC) ? srcb[r0] : tgt[b * NTGT + r0 - NSRC];
        float2 X1 = (li < NSRC) ? srcb[r1] : tgt[b * NTGT + r1 - NSRC];
        const ull xp0 = pack2(X0.x, X0.x), yp0 = pack2(X0.y, X0.y);
        const ull xp1 = pack2(X1.x, X1.x), yp1 = pack2(X1.y, X1.y);
        float c0 = c2 * (X0.x * X0.x + X0.y * X0.y);
        float c1 = c2 * (X1.x * X1.x + X1.y * X1.y);
        const ull cr0 = pack2(c0, c0), cr1 = pack2(c1, c1);

        ull ax0 = 0ull, ay0 = 0ull, ax1 = 0ull, ay1 = 0ull;
        const int qb = w * 64;
        #pragma unroll 2
        for (int t = 0; t < 64; t += 4) {    // 3 MUFU steps + 1 fast step
            rbf_step<true >(sUV, sAP, sPY, qb + t,     xp0, yp0, cr0, xp1, yp1, cr1, C, ax0, ay0, ax1, ay1);
            rbf_step<true >(sUV, sAP, sPY, qb + t + 1, xp0, yp0, cr0, xp1, yp1, cr1, C, ax0, ay0, ax1, ay1);
            rbf_step<true >(sUV, sAP, sPY, qb + t + 2, xp0, yp0, cr0, xp1, yp1, cr1, C, ax0, ay0, ax1, ay1);
            rbf_step<false>(sUV, sAP, sPY, qb + t + 3, xp0, yp0, cr0, xp1, yp1, cr1, C, ax0, ay0, ax1, ay1);
        }
        __syncthreads();                      // table reads done; red aliases sUV
        red[0][w * 32 + lane] = ax0;
        red[1][w * 32 + lane] = ay0;
        red[2][w * 32 + lane] = ax1;
        red[3][w * 32 + lane] = ay1;
        __syncthreads();

        if (w == 0) {
            ull s0 = red[0][lane], s1 = red[1][lane];
            ull s2 = red[2][lane], s3 = red[3][lane];
            #pragma unroll
            for (int ww = 1; ww < 8; ww++) {
                s0 = add2(s0, red[0][ww * 32 + lane]);
                s1 = add2(s1, red[1][ww * 32 + lane]);
                s2 = add2(s2, red[2][ww * 32 + lane]);
                s3 = add2(s3, red[3][ww * 32 + lane]);
            }
            float e0, e1, f0, f1;
            unpack2(s0, e0, e1); unpack2(s1, f0, f1);
            g_p1[sj][i0 + lane] = make_float2(e0 + e1, f0 + f1);
            unpack2(s2, e0, e1); unpack2(s3, f0, f1);
            g_p1[sj][i0 + 32 + lane] = make_float2(e0 + e1, f0 + f1);
        }
    }

    // ======================= Grid barrier =======================
    __threadfence();
    __syncthreads();
    if (tid == 0) {
        ull old = atomicAdd(&g_ctr, 1ull);
        ull target = (old & ~(ull)(NCTA - 1)) + (ull)NCTA;
        while (*(volatile ull*)&g_ctr < target) __nanosleep(64);
        __threadfence();
    }
    __syncthreads();

    // ======================= Phase B: dp2 + output =======================
    {
        const int grp = g >> 2;              // 0..127: 64-row target group
        const int sj  = g & 3;               // j-quarter
        const int t0  = grp * 64;            // global target row base
        const int b   = t0 >> 11;

        // Stage 256 pairs, rebuilding shape1 pack from dp1 partials.
        {
            const int q = tid;               // 256 threads, 256 entries
            const int p = sj * 256 + q;      // pair within batch
            const int j0 = 2 * p, j1 = 2 * p + 1;
            const int l0 = b * NLAND + j0, l1 = b * NLAND + j1;
            float2 pa0 = g_p1[0][l0], pb0 = g_p1[1][l0];
            float2 pa1 = g_p1[0][l1], pb1 = g_p1[1][l1];
            float2 s0 = src[b * NSRC + j0], s1 = src[b * NSRC + j1];
            float2 q0 = mom[b * NSRC + j0], q1 = mom[b * NSRC + j1];
            float s0x = fmaf(TAUF, pa0.x + pb0.x, s0.x);
            float s0y = fmaf(TAUF, pa0.y + pb0.y, s0.y);
            float s1x = fmaf(TAUF, pa1.x + pb1.x, s1.x);
            float s1y = fmaf(TAUF, pa1.y + pb1.y, s1.y);
            sUV[q] = make_float4(m2 * s0x, m2 * s1x, m2 * s0y, m2 * s1y);
            sAP[q] = make_float4(c2 * (s0x * s0x + s0y * s0y),
                                 c2 * (s1x * s1x + s1y * s1y), q0.x, q1.x);
            sPY[q] = make_float2(q0.y, q1.y);
        }
        __syncthreads();

        // This lane's two target rows, advected to shape1.
        const int ta = t0 + lane, tb2 = ta + 32;
        const int rta = ta & (NTGT - 1), rtb = tb2 & (NTGT - 1);
        const int la = b * NLAND + NSRC + rta, lb = b * NLAND + NSRC + rtb;
        float2 Ta = tgt[ta], Tb = tgt[tb2];
        float2 da0 = g_p1[0][la], da1 = g_p1[1][la];
        float2 db0 = g_p1[0][lb], db1 = g_p1[1][lb];
        float2 X0 = make_float2(fmaf(TAUF, da0.x + da1.x, Ta.x),
                                fmaf(TAUF, da0.y + da1.y, Ta.y));
        float2 X1 = make_float2(fmaf(TAUF, db0.x + db1.x, Tb.x),
                                fmaf(TAUF, db0.y + db1.y, Tb.y));
        const ull xp0 = pack2(X0.x, X0.x), yp0 = pack2(X0.y, X0.y);
        const ull xp1 = pack2(X1.x, X1.x), yp1 = pack2(X1.y, X1.y);
        float c0 = c2 * (X0.x * X0.x + X0.y * X0.y);
        float c1 = c2 * (X1.x * X1.x + X1.y * X1.y);
        const ull cr0 = pack2(c0, c0), cr1 = pack2(c1, c1);

        ull ax0 = 0ull, ay0 = 0ull, ax1 = 0ull, ay1 = 0ull;
        const int qb = w * 32;
        #pragma unroll 2
        for (int t = 0; t < 32; t += 4) {    // 3 MUFU steps + 1 fast step
            rbf_step<true >(sUV, sAP, sPY, qb + t,     xp0, yp0, cr0, xp1, yp1, cr1, C, ax0, ay0, ax1, ay1);
            rbf_step<true >(sUV, sAP, sPY, qb + t + 1, xp0, yp0, cr0, xp1, yp1, cr1, C, ax0, ay0, ax1, ay1);
            rbf_step<true >(sUV, sAP, sPY, qb + t + 2, xp0, yp0, cr0, xp1, yp1, cr1, C, ax0, ay0, ax1, ay1);
            rbf_step<false>(sUV, sAP, sPY, qb + t + 3, xp0, yp0, cr0, xp1, yp1, cr1, C, ax0, ay0, ax1, ay1);
        }
        __syncthreads();                      // table reads done; red aliases sUV
        red[0][w * 32 + lane] = ax0;
        red[1][w * 32 + lane] = ay0;
        red[2][w * 32 + lane] = ax1;
        red[3][w * 32 + lane] = ay1;
        __syncthreads();

        if (w == 0) {
            ull s0 = red[0][lane], s1 = red[1][lane];
            ull s2 = red[2][lane], s3 = red[3][lane];
            #pragma unroll
            for (int ww = 1; ww < 8; ww++) {
                s0 = add2(s0, red[0][ww * 32 + lane]);
                s1 = add2(s1, red[1][ww * 32 + lane]);
                s2 = add2(s2, red[2][ww * 32 + lane]);
                s3 = add2(s3, red[3][ww * 32 + lane]);
            }
            float e0, e1, f0, f1;
            unpack2(s0, e0, e1); unpack2(s1, f0, f1);
            g_p2[sj][ta] = make_float2(e0 + e1, f0 + f1);
            unpack2(s2, e0, e1); unpack2(s3, f0, f1);
            g_p2[sj][tb2] = make_float2(e0 + e1, f0 + f1);

            __threadfence();                  // release partials
            __syncwarp();
            unsigned old = 0;
            if (lane == 0) old = atomicAdd(&g_flag[grp], 1u);
            old = __shfl_sync(0xffffffffu, old, 0);
            if ((old & 3u) == 3u) {           // 4th arrival: combine + writeout
                __threadfence();              // acquire peer partials
                float2 p0 = __ldcg(&g_p2[0][ta]);
                float2 p1 = __ldcg(&g_p2[1][ta]);
                float2 p2 = __ldcg(&g_p2[2][ta]);
                float2 p3 = __ldcg(&g_p2[3][ta]);
                out[ta] = make_float2(
                    fmaf(TAUF, (p0.x + p1.x) + (p2.x + p3.x), X0.x),
                    fmaf(TAUF, (p0.y + p1.y) + (p2.y + p3.y), X0.y));
                p0 = __ldcg(&g_p2[0][tb2]);
                p1 = __ldcg(&g_p2[1][tb2]);
                p2 = __ldcg(&g_p2[2][tb2]);
                p3 = __ldcg(&g_p2[3][tb2]);
                out[tb2] = make_float2(
                    fmaf(TAUF, (p0.x + p1.x) + (p2.x + p3.x), X1.x),
                    fmaf(TAUF, (p0.y + p1.y) + (p2.y + p3.y), X1.y));
            }
        }
    }
}

// ---------------------------------------------------------------------------
extern "C" void kernel_launch(void* const* d_in, const int* in_sizes, int n_in,
                              void* d_out, int out_size)
{
    const float2* mom = (const float2*)d_in[0];
    const float2* src = (const float2*)d_in[1];
    const float2* tgt = (const float2*)d_in[2];
    const float*  sig = (const float*)d_in[3];
    float2* out = (float2*)d_out;

    fused_kernel<<<NCTA, 256>>>(mom, src, tgt, sig, out);
}

// round 15
// speedup vs baseline: 1.2540x; 1.1006x over previous
#include <cuda_runtime.h>

// Two Euler steps of a Gaussian-RBF point flow — single persistent kernel.
// R15 = R10 (best measured: 26.6us total / 25.4 in-kernel) with overhead
// trims only. The x-sweep (R10/R14/R13: 25.4/28.0/31.2 at x=0/.25/.5)
// proved dur rises LINEARLY with any fma-path exp offload => R10 sits at
// the ex2.approx.f32 throughput floor (~22.4us) and pipe rebalancing can't
// beat it. All exps on MUFU; trims: unroll 8 mainloops, lighter barrier
// spin, compacted phase-B epilogue.
//   Phase A: dp1 PARTIALS for all 16384 land rows. 512 CTAs x 256 thr:
//            CTA = 64 rows x half the j-range (512 pairs, 64 steps/warp).
//   Grid barrier (monotonic counter; 512 CTAs resident at 4 CTAs/SM).
//   Phase B: dp2. CTA = 64 target rows x quarter j-range; staging rebuilds
//            shape1-packed tables from dp1 partials; 4-way parity combine.
// Row-block x2: each lane owns 2 rows; FFMA2 packs PAIRS of source points;
// one 40B table load serves 2 rows x 2 j.
// Inner exponent: safe combined form arg = u*x + v*y + a + cri <= 0.

#define NSRC  2048
#define NTGT  2048
#define NLAND 4096
#define NB    4
#define NCTA  512
#define TAUF  0.5f
#define LOG2E 1.4426950408889634f

typedef unsigned long long ull;

// Cross-phase scratch (device globals; no allocation).
__device__ float2 g_p1[2][NB * NLAND];   // dp1 partials per j-half
__device__ float2 g_p2[4][NB * NTGT];    // dp2 partials per j-quarter
__device__ ull      g_ctr;               // grid barrier, monotonic across calls
__device__ unsigned g_flag[128];         // per-group arrival count, monotonic

__device__ __forceinline__ float ex2f(float x) {
    float y;
    asm("ex2.approx.ftz.f32 %0, %1;" : "=f"(y) : "f"(x));
    return y;
}
__device__ __forceinline__ ull fma2(ull a, ull b, ull c) {
    ull d;
    asm("fma.rn.f32x2 %0, %1, %2, %3;" : "=l"(d) : "l"(a), "l"(b), "l"(c));
    return d;
}
__device__ __forceinline__ ull add2(ull a, ull b) {
    ull d;
    asm("add.rn.f32x2 %0, %1, %2;" : "=l"(d) : "l"(a), "l"(b));
    return d;
}
__device__ __forceinline__ ull pack2(float lo, float hi) {
    ull d;
    asm("mov.b64 %0, {%1, %2};" : "=l"(d) : "f"(lo), "f"(hi));
    return d;
}
__device__ __forceinline__ void unpack2(ull v, float& lo, float& hi) {
    asm("mov.b64 {%0, %1}, %2;" : "=f"(lo), "=f"(hi) : "l"(v));
}

// One row's packed update for a loaded j-pair (all exps on MUFU).
__device__ __forceinline__ void rbf_row(
    ull UVx, ull UVy, ull APa, ull APp, ull PY,
    ull xp, ull yp, ull crip, ull& ax, ull& ay)
{
    ull arg = add2(fma2(UVy, yp, fma2(UVx, xp, APa)), crip);
    float a0, a1;
    unpack2(arg, a0, a1);
    ull wp = pack2(ex2f(a0), ex2f(a1));
    ax = fma2(wp, APp, ax);
    ay = fma2(wp, PY, ay);
}

// ---------------------------------------------------------------------------
__global__ __launch_bounds__(256, 4) void fused_kernel(
    const float2* __restrict__ mom,
    const float2* __restrict__ src,
    const float2* __restrict__ tgt,
    const float*  __restrict__ sig,
    float2*       __restrict__ out)
{
    // Layout: sUV [0,8K) | sAP [8K,16K) | sPY [16K,20K).
    // Reduction buffer (8KB) aliases sUV after a syncthreads.
    __shared__ __align__(16) char SM[20480];
    float4* sUV = (float4*)(SM);
    float4* sAP = (float4*)(SM + 8192);
    float2* sPY = (float2*)(SM + 16384);
    typedef ull RedRow[256];                 // [warp*32+lane]
    RedRow* red = (RedRow*)(SM);             // red[4][256] = 8KB, aliases sUV

    const int tid  = threadIdx.x;
    const int w    = tid >> 5;
    const int lane = tid & 31;
    const int g    = blockIdx.x;

    const float c2 = -LOG2E / sig[0];
    const float m2 = -2.0f * c2;

    // ======================= Phase A: dp1 partials =======================
    {
        const int grp = g >> 1;              // 0..255: 64-row land group
        const int sj  = g & 1;               // j-half
        const int i0  = grp * 64;            // global land row base
        const int b   = i0 >> 12;
        const int li  = i0 & (NLAND - 1);

        const float2* __restrict__ srcb = src + b * NSRC;
        const float2* __restrict__ momb = mom + b * NSRC;

        const int pbase = sj * 512;          // pair range [pbase, pbase+512)
        for (int q = tid; q < 512; q += 256) {
            const int p = pbase + q;
            float2 s0 = srcb[2 * p], s1 = srcb[2 * p + 1];
            float2 q0 = momb[2 * p], q1 = momb[2 * p + 1];
            sUV[q] = make_float4(m2 * s0.x, m2 * s1.x, m2 * s0.y, m2 * s1.y);
            sAP[q] = make_float4(c2 * (s0.x * s0.x + s0.y * s0.y),
                                 c2 * (s1.x * s1.x + s1.y * s1.y), q0.x, q1.x);
            sPY[q] = make_float2(q0.y, q1.y);
        }
        __syncthreads();

        const int r0 = li + lane, r1 = r0 + 32;     // same side of 2048
        float2 X0 = (li < NSRC) ? srcb[r0] : tgt[b * NTGT + r0 - NSRC];
        float2 X1 = (li < NSRC) ? srcb[r1] : tgt[b * NTGT + r1 - NSRC];
        const ull xp0 = pack2(X0.x, X0.x), yp0 = pack2(X0.y, X0.y);
        const ull xp1 = pack2(X1.x, X1.x), yp1 = pack2(X1.y, X1.y);
        float c0 = c2 * (X0.x * X0.x + X0.y * X0.y);
        float c1 = c2 * (X1.x * X1.x + X1.y * X1.y);
        const ull cr0 = pack2(c0, c0), cr1 = pack2(c1, c1);

        ull ax0 = 0ull, ay0 = 0ull, ax1 = 0ull, ay1 = 0ull;
        const int qb = w * 64;
        #pragma unroll 8
        for (int t = 0; t < 64; t++) {
            ulonglong2 UV = *(const ulonglong2*)&sUV[qb + t];
            ulonglong2 AP = *(const ulonglong2*)&sAP[qb + t];
            ull PY = *(const ull*)&sPY[qb + t];
            rbf_row(UV.x, UV.y, AP.x, AP.y, PY, xp0, yp0, cr0, ax0, ay0);
            rbf_row(UV.x, UV.y, AP.x, AP.y, PY, xp1, yp1, cr1, ax1, ay1);
        }
        __syncthreads();                      // table reads done; red aliases sUV
        red[0][w * 32 + lane] = ax0;
        red[1][w * 32 + lane] = ay0;
        red[2][w * 32 + lane] = ax1;
        red[3][w * 32 + lane] = ay1;
        __syncthreads();

        if (w == 0) {
            ull s0 = red[0][lane], s1 = red[1][lane];
            ull s2 = red[2][lane], s3 = red[3][lane];
            #pragma unroll
            for (int ww = 1; ww < 8; ww++) {
                s0 = add2(s0, red[0][ww * 32 + lane]);
                s1 = add2(s1, red[1][ww * 32 + lane]);
                s2 = add2(s2, red[2][ww * 32 + lane]);
                s3 = add2(s3, red[3][ww * 32 + lane]);
            }
            float e0, e1, f0, f1;
            unpack2(s0, e0, e1); unpack2(s1, f0, f1);
            g_p1[sj][i0 + lane] = make_float2(e0 + e1, f0 + f1);
            unpack2(s2, e0, e1); unpack2(s3, f0, f1);
            g_p1[sj][i0 + 32 + lane] = make_float2(e0 + e1, f0 + f1);
        }
    }

    // ======================= Grid barrier =======================
    __threadfence();
    __syncthreads();
    if (tid == 0) {
        ull old = atomicAdd(&g_ctr, 1ull);
        ull target = (old & ~(ull)(NCTA - 1)) + (ull)NCTA;
        while (*(volatile ull*)&g_ctr < target) __nanosleep(32);
        __threadfence();
    }
    __syncthreads();

    // ======================= Phase B: dp2 + output =======================
    {
        const int grp = g >> 2;              // 0..127: 64-row target group
        const int sj  = g & 3;               // j-quarter
        const int t0  = grp * 64;            // global target row base
        const int b   = t0 >> 11;

        // Stage 256 pairs, rebuilding shape1 pack from dp1 partials.
        {
            const int q = tid;               // 256 threads, 256 entries
            const int p = sj * 256 + q;      // pair within batch
            const int j0 = 2 * p, j1 = 2 * p + 1;
            const int l0 = b * NLAND + j0, l1 = b * NLAND + j1;
            float2 pa0 = g_p1[0][l0], pb0 = g_p1[1][l0];
            float2 pa1 = g_p1[0][l1], pb1 = g_p1[1][l1];
            float2 s0 = src[b * NSRC + j0], s1 = src[b * NSRC + j1];
            float2 q0 = mom[b * NSRC + j0], q1 = mom[b * NSRC + j1];
            float s0x = fmaf(TAUF, pa0.x + pb0.x, s0.x);
            float s0y = fmaf(TAUF, pa0.y + pb0.y, s0.y);
            float s1x = fmaf(TAUF, pa1.x + pb1.x, s1.x);
            float s1y = fmaf(TAUF, pa1.y + pb1.y, s1.y);
            sUV[q] = make_float4(m2 * s0x, m2 * s1x, m2 * s0y, m2 * s1y);
            sAP[q] = make_float4(c2 * (s0x * s0x + s0y * s0y),
                                 c2 * (s1x * s1x + s1y * s1y), q0.x, q1.x);
            sPY[q] = make_float2(q0.y, q1.y);
        }
        __syncthreads();

        // This lane's two target rows, advected to shape1.
        const int ta = t0 + lane, tb2 = ta + 32;
        const int rta = ta & (NTGT - 1), rtb = tb2 & (NTGT - 1);
        const int la = b * NLAND + NSRC + rta, lb = b * NLAND + NSRC + rtb;
        float2 Ta = tgt[ta], Tb = tgt[tb2];
        float2 da0 = g_p1[0][la], da1 = g_p1[1][la];
        float2 db0 = g_p1[0][lb], db1 = g_p1[1][lb];
        float2 X0 = make_float2(fmaf(TAUF, da0.x + da1.x, Ta.x),
                                fmaf(TAUF, da0.y + da1.y, Ta.y));
        float2 X1 = make_float2(fmaf(TAUF, db0.x + db1.x, Tb.x),
                                fmaf(TAUF, db0.y + db1.y, Tb.y));
        const ull xp0 = pack2(X0.x, X0.x), yp0 = pack2(X0.y, X0.y);
        const ull xp1 = pack2(X1.x, X1.x), yp1 = pack2(X1.y, X1.y);
        float c0 = c2 * (X0.x * X0.x + X0.y * X0.y);
        float c1 = c2 * (X1.x * X1.x + X1.y * X1.y);
        const ull cr0 = pack2(c0, c0), cr1 = pack2(c1, c1);

        ull ax0 = 0ull, ay0 = 0ull, ax1 = 0ull, ay1 = 0ull;
        const int qb = w * 32;
        #pragma unroll 8
        for (int t = 0; t < 32; t++) {
            ulonglong2 UV = *(const ulonglong2*)&sUV[qb + t];
            ulonglong2 AP = *(const ulonglong2*)&sAP[qb + t];
            ull PY = *(const ull*)&sPY[qb + t];
            rbf_row(UV.x, UV.y, AP.x, AP.y, PY, xp0, yp0, cr0, ax0, ay0);
            rbf_row(UV.x, UV.y, AP.x, AP.y, PY, xp1, yp1, cr1, ax1, ay1);
        }
        __syncthreads();                      // table reads done; red aliases sUV
        red[0][w * 32 + lane] = ax0;
        red[1][w * 32 + lane] = ay0;
        red[2][w * 32 + lane] = ax1;
        red[3][w * 32 + lane] = ay1;
        __syncthreads();

        if (w == 0) {
            ull s0 = red[0][lane], s1 = red[1][lane];
            ull s2 = red[2][lane], s3 = red[3][lane];
            #pragma unroll
            for (int ww = 1; ww < 8; ww++) {
                s0 = add2(s0, red[0][ww * 32 + lane]);
                s1 = add2(s1, red[1][ww * 32 + lane]);
                s2 = add2(s2, red[2][ww * 32 + lane]);
                s3 = add2(s3, red[3][ww * 32 + lane]);
            }
            float e0, e1, f0, f1;
            unpack2(s0, e0, e1); unpack2(s1, f0, f1);
            g_p2[sj][ta] = make_float2(e0 + e1, f0 + f1);
            unpack2(s2, e0, e1); unpack2(s3, f0, f1);
            g_p2[sj][tb2] = make_float2(e0 + e1, f0 + f1);

            __threadfence();                  // release partials
            __syncwarp();
            unsigned old = 0;
            if (lane == 0) old = atomicAdd(&g_flag[grp], 1u);
            old = __shfl_sync(0xffffffffu, old, 0);
            if ((old & 3u) == 3u) {           // 4th arrival: combine + writeout
                __threadfence();              // acquire peer partials
                float2 a0 = __ldcg(&g_p2[0][ta]),  a1 = __ldcg(&g_p2[1][ta]);
                float2 a2 = __ldcg(&g_p2[2][ta]),  a3 = __ldcg(&g_p2[3][ta]);
                float2 b0 = __ldcg(&g_p2[0][tb2]), b1 = __ldcg(&g_p2[1][tb2]);
                float2 b2 = __ldcg(&g_p2[2][tb2]), b3 = __ldcg(&g_p2[3][tb2]);
                out[ta] = make_float2(
                    fmaf(TAUF, (a0.x + a1.x) + (a2.x + a3.x), X0.x),
                    fmaf(TAUF, (a0.y + a1.y) + (a2.y + a3.y), X0.y));
                out[tb2] = make_float2(
                    fmaf(TAUF, (b0.x + b1.x) + (b2.x + b3.x), X1.x),
                    fmaf(TAUF, (b0.y + b1.y) + (b2.y + b3.y), X1.y));
            }
        }
    }
}

// ---------------------------------------------------------------------------
extern "C" void kernel_launch(void* const* d_in, const int* in_sizes, int n_in,
                              void* d_out, int out_size)
{
    const float2* mom = (const float2*)d_in[0];
    const float2* src = (const float2*)d_in[1];
    const float2* tgt = (const float2*)d_in[2];
    const float*  sig = (const float*)d_in[3];
    float2* out = (float2*)d_out;

    fused_kernel<<<NCTA, 256>>>(mom, src, tgt, sig, out);
}